// round 3
// baseline (speedup 1.0000x reference)
#include <cuda_runtime.h>
#include <cstdint>

// Problem constants
#define BATCH 4
#define NY 16384
#define NX 4096
#define CY 128
#define CX 256
#define DIMF 384       // CY + CX
#define C1 512
#define C2 256
#define C3 128
#define MTOT (BATCH*NY)   // 65536
#define IEPS 1e-8f
#define BN_EPS 1e-5f

// ---------------- scratch (device globals; no runtime alloc) ----------------
__device__ float g_feat[(size_t)MTOT * DIMF];   // 100.7 MB
__device__ float g_z1[(size_t)MTOT * C1];       // 134 MB
__device__ float g_z2[(size_t)MTOT * C2];       // 67 MB
__device__ float g_z3[(size_t)MTOT * C3];       // 33.5 MB
__device__ float g_red[1792];
__device__ float g_aff[1792];

// ---------------- zero kernel ----------------
__global__ void zero_kernel(float* __restrict__ p, int n) {
    int i = blockIdx.x * blockDim.x + threadIdx.x;
    if (i < n) p[i] = 0.0f;
}

// ---------------- KNN + interpolation + concat ----------------
// Distance arithmetic replicates the reference fp32 op-tree exactly:
//   psq = (y0*y0 + y1*y1) + y2*y2          (rounded mul, left-to-right add)
//   dot = fma(y2,x2, fma(y1,x1, rnd(y0*x0)))  (ascending-k FMA chain)
//   d   = (psq + xsq) - (2*dot)            (separate mul and sub, no fma)
// grid: (NY/256, BATCH), block 256
#define NXC 2048
__global__ __launch_bounds__(256)
void knn_interp_kernel(const float* __restrict__ yp, const float* __restrict__ yf,
                       const float* __restrict__ xp, const float* __restrict__ xf,
                       float* __restrict__ feat)
{
    __shared__ float4 s_pt[NXC];   // 32 KB: coords + |x|^2
    int b = blockIdx.y;
    int tid = threadIdx.x;
    int n = blockIdx.x * 256 + tid;
    int m = b * NY + n;

    const float* xpb = xp + (size_t)b * NX * 3;
    float px = yp[(size_t)m * 3 + 0];
    float py = yp[(size_t)m * 3 + 1];
    float pz = yp[(size_t)m * 3 + 2];
    float psq = __fadd_rn(__fadd_rn(__fmul_rn(px, px), __fmul_rn(py, py)),
                          __fmul_rn(pz, pz));

    float d0 = 3.4e38f, d1 = 3.4e38f, d2 = 3.4e38f;
    int i0 = 0, i1 = 0, i2 = 0;

    for (int ch = 0; ch < NX; ch += NXC) {
        __syncthreads();
        for (int j = tid; j < NXC; j += 256) {
            const float* xq = xpb + 3 * (size_t)(ch + j);
            float x = xq[0], y = xq[1], z = xq[2];
            float xsq = __fadd_rn(__fadd_rn(__fmul_rn(x, x), __fmul_rn(y, y)),
                                  __fmul_rn(z, z));
            s_pt[j] = make_float4(x, y, z, xsq);
        }
        __syncthreads();
        #pragma unroll 8
        for (int j = 0; j < NXC; j++) {
            float4 q = s_pt[j];
            // ascending-k FMA accumulation: fma(k2, fma(k1, rnd(k0)))
            float dot = __fmaf_rn(pz, q.z, __fmaf_rn(py, q.y, __fmul_rn(px, q.x)));
            // (psq + xsq) - (2*dot): separate rounded ops, no contraction
            float d = __fsub_rn(__fadd_rn(psq, q.w), __fmul_rn(2.0f, dot));
            if (d < d2) {
                int jj = ch + j;
                if (d < d1) {
                    d2 = d1; i2 = i1;
                    if (d < d0) { d1 = d0; i1 = i0; d0 = d; i0 = jj; }
                    else        { d1 = d;  i1 = jj; }
                } else { d2 = d; i2 = jj; }
            }
        }
    }

    float w0 = 1.0f / (d0 + IEPS);
    float w1 = 1.0f / (d1 + IEPS);
    float w2 = 1.0f / (d2 + IEPS);
    float ws = 1.0f / (w0 + w1 + w2);
    w0 *= ws; w1 *= ws; w2 *= ws;

    // warp-cooperative feature gather + concat (coalesced)
    int lane = tid & 31;
    const float* xfb = xf + (size_t)b * NX * CX;
    unsigned mask = 0xffffffffu;
    for (int s = 0; s < 32; s++) {
        int   j0 = __shfl_sync(mask, i0, s);
        int   j1 = __shfl_sync(mask, i1, s);
        int   j2 = __shfl_sync(mask, i2, s);
        float a0 = __shfl_sync(mask, w0, s);
        float a1 = __shfl_sync(mask, w1, s);
        float a2 = __shfl_sync(mask, w2, s);
        int ms = m - lane + s;
        float* frow = feat + (size_t)ms * DIMF;
        const float4* ysrc = (const float4*)(yf + (size_t)ms * CY);
        ((float4*)frow)[lane] = ysrc[lane];
        const float4* r0 = (const float4*)(xfb + (size_t)j0 * CX);
        const float4* r1 = (const float4*)(xfb + (size_t)j1 * CX);
        const float4* r2 = (const float4*)(xfb + (size_t)j2 * CX);
        float4* dst = (float4*)(frow + CY);
        #pragma unroll
        for (int h = 0; h < 2; h++) {
            int c4 = h * 32 + lane;
            float4 v0 = r0[c4], v1 = r1[c4], v2 = r2[c4];
            float4 o;
            o.x = a0 * v0.x + a1 * v1.x + a2 * v2.x;
            o.y = a0 * v0.y + a1 * v1.y + a2 * v2.y;
            o.z = a0 * v0.z + a1 * v1.z + a2 * v2.z;
            o.w = a0 * v0.w + a1 * v1.w + a2 * v2.w;
            dst[c4] = o;
        }
    }
}

// ---------------- tiled SGEMM (exact fp32):  C = act(A) @ W^T + bias ----------------
template<bool NORM>
__global__ __launch_bounds__(256, 2)
void gemm_kernel(const float* __restrict__ A, const float* __restrict__ W,
                 const float* __restrict__ bias,
                 const float* __restrict__ scale, const float* __restrict__ shift,
                 float* __restrict__ Cmat, int Kdim, int Ndim)
{
    __shared__ float As[16][132];
    __shared__ float Bs[16][132];

    int tid = threadIdx.x;
    int m0 = blockIdx.y * 128;
    int n0 = blockIdx.x * 128;
    int ty = tid >> 4, tx = tid & 15;

    float acc[8][8];
    #pragma unroll
    for (int i = 0; i < 8; i++)
        #pragma unroll
        for (int j = 0; j < 8; j++) acc[i][j] = 0.0f;

    const float* Aptr = A + (size_t)m0 * Kdim;
    const float* Wptr = W + (size_t)n0 * Kdim;
    int fA = tid * 2;

    for (int k0 = 0; k0 < Kdim; k0 += 16) {
        #pragma unroll
        for (int i = 0; i < 2; i++) {
            int f = fA + i;
            int row = f >> 2;
            int kq = (f & 3) * 4;
            float4 v = *(const float4*)(Aptr + (size_t)row * Kdim + k0 + kq);
            if (NORM) {
                int k = k0 + kq;
                v.x = fmaxf(fmaf(scale[k + 0], v.x, shift[k + 0]), 0.0f);
                v.y = fmaxf(fmaf(scale[k + 1], v.y, shift[k + 1]), 0.0f);
                v.z = fmaxf(fmaf(scale[k + 2], v.z, shift[k + 2]), 0.0f);
                v.w = fmaxf(fmaf(scale[k + 3], v.w, shift[k + 3]), 0.0f);
            }
            As[kq + 0][row] = v.x; As[kq + 1][row] = v.y;
            As[kq + 2][row] = v.z; As[kq + 3][row] = v.w;
            float4 u = *(const float4*)(Wptr + (size_t)row * Kdim + k0 + kq);
            Bs[kq + 0][row] = u.x; Bs[kq + 1][row] = u.y;
            Bs[kq + 2][row] = u.z; Bs[kq + 3][row] = u.w;
        }
        __syncthreads();
        #pragma unroll
        for (int kk = 0; kk < 16; kk++) {
            float a[8], bb[8];
            *(float4*)(a)      = *(const float4*)&As[kk][ty * 8];
            *(float4*)(a + 4)  = *(const float4*)&As[kk][ty * 8 + 4];
            *(float4*)(bb)     = *(const float4*)&Bs[kk][tx * 8];
            *(float4*)(bb + 4) = *(const float4*)&Bs[kk][tx * 8 + 4];
            #pragma unroll
            for (int i = 0; i < 8; i++)
                #pragma unroll
                for (int j = 0; j < 8; j++)
                    acc[i][j] = fmaf(a[i], bb[j], acc[i][j]);
        }
        __syncthreads();
    }

    float bv[8];
    #pragma unroll
    for (int j = 0; j < 8; j++) bv[j] = bias[n0 + tx * 8 + j];

    #pragma unroll
    for (int i = 0; i < 8; i++) {
        int r = m0 + ty * 8 + i;
        float* crow = Cmat + (size_t)r * Ndim + n0 + tx * 8;
        float4 o1, o2;
        o1.x = acc[i][0] + bv[0]; o1.y = acc[i][1] + bv[1];
        o1.z = acc[i][2] + bv[2]; o1.w = acc[i][3] + bv[3];
        o2.x = acc[i][4] + bv[4]; o2.y = acc[i][5] + bv[5];
        o2.z = acc[i][6] + bv[6]; o2.w = acc[i][7] + bv[7];
        *(float4*)(crow)     = o1;
        *(float4*)(crow + 4) = o2;
    }
}

// ---------------- per-channel sum / sumsq reduction ----------------
__global__ __launch_bounds__(256)
void stats_kernel(const float* __restrict__ Z, int Cdim,
                  float* __restrict__ sum, float* __restrict__ sq)
{
    int r0 = blockIdx.x * 128;
    for (int c = threadIdx.x; c < Cdim; c += 256) {
        float s = 0.0f, q = 0.0f;
        const float* p = Z + (size_t)r0 * Cdim + c;
        #pragma unroll 4
        for (int r = 0; r < 128; r++) {
            float v = p[(size_t)r * Cdim];
            s += v;
            q = fmaf(v, v, q);
        }
        atomicAdd(&sum[c], s);
        atomicAdd(&sq[c], q);
    }
}

// ---------------- finalize BN affine ----------------
__global__ void finalize_kernel(const float* __restrict__ sum, const float* __restrict__ sq,
                                const float* __restrict__ g, const float* __restrict__ be,
                                float* __restrict__ scale, float* __restrict__ shift, int Cdim)
{
    int c = blockIdx.x * blockDim.x + threadIdx.x;
    if (c < Cdim) {
        const float invM = 1.0f / (float)MTOT;
        float mean = sum[c] * invM;
        float var  = sq[c] * invM - mean * mean;
        float inv  = rsqrtf(var + BN_EPS);
        float sc   = g[c] * inv;
        scale[c] = sc;
        shift[c] = be[c] - mean * sc;
    }
}

// ---------------- final: normalize+relu layer3 and transpose to [B, C3, NY] ----------------
__global__ __launch_bounds__(256)
void trans_norm_kernel(const float* __restrict__ z3, const float* __restrict__ sc,
                       const float* __restrict__ sh, float* __restrict__ out)
{
    __shared__ float tile[32][33];
    int m0 = blockIdx.x * 32;
    int c0 = blockIdx.y * 32;
    int tx = threadIdx.x, ty = threadIdx.y;
    #pragma unroll
    for (int r = ty; r < 32; r += 8) {
        int c = c0 + tx;
        float v = z3[(size_t)(m0 + r) * C3 + c];
        v = fmaxf(fmaf(sc[c], v, sh[c]), 0.0f);
        tile[r][tx] = v;
    }
    __syncthreads();
    int b = m0 / NY;
    int n0 = m0 - b * NY;
    #pragma unroll
    for (int r = ty; r < 32; r += 8) {
        out[((size_t)b * C3 + c0 + r) * NY + n0 + tx] = tile[tx][r];
    }
}

// ---------------- launch ----------------
extern "C" void kernel_launch(void* const* d_in, const int* in_sizes, int n_in,
                              void* d_out, int out_size)
{
    const float* y_points = (const float*)d_in[0];
    const float* y_feats  = (const float*)d_in[1];
    const float* x_points = (const float*)d_in[2];
    const float* x_feats  = (const float*)d_in[3];
    const float* W1 = (const float*)d_in[4];
    const float* b1 = (const float*)d_in[5];
    const float* g1 = (const float*)d_in[6];
    const float* be1 = (const float*)d_in[7];
    const float* W2 = (const float*)d_in[8];
    const float* b2 = (const float*)d_in[9];
    const float* g2 = (const float*)d_in[10];
    const float* be2 = (const float*)d_in[11];
    const float* W3 = (const float*)d_in[12];
    const float* b3 = (const float*)d_in[13];
    const float* g3 = (const float*)d_in[14];
    const float* be3 = (const float*)d_in[15];
    float* out = (float*)d_out;

    float *feat, *z1, *z2, *z3, *red, *aff;
    cudaGetSymbolAddress((void**)&feat, g_feat);
    cudaGetSymbolAddress((void**)&z1, g_z1);
    cudaGetSymbolAddress((void**)&z2, g_z2);
    cudaGetSymbolAddress((void**)&z3, g_z3);
    cudaGetSymbolAddress((void**)&red, g_red);
    cudaGetSymbolAddress((void**)&aff, g_aff);

    float* sum1 = red + 0;    float* sq1 = red + 512;
    float* sum2 = red + 1024; float* sq2 = red + 1280;
    float* sum3 = red + 1536; float* sq3 = red + 1664;
    float* sc1 = aff + 0;     float* sh1 = aff + 512;
    float* sc2 = aff + 1024;  float* sh2 = aff + 1280;
    float* sc3 = aff + 1536;  float* sh3 = aff + 1664;

    zero_kernel<<<7, 256>>>(red, 1792);

    knn_interp_kernel<<<dim3(NY / 256, BATCH), 256>>>(y_points, y_feats, x_points, x_feats, feat);

    gemm_kernel<false><<<dim3(C1 / 128, MTOT / 128), 256>>>(feat, W1, b1, nullptr, nullptr, z1, DIMF, C1);
    stats_kernel<<<MTOT / 128, 256>>>(z1, C1, sum1, sq1);
    finalize_kernel<<<2, 256>>>(sum1, sq1, g1, be1, sc1, sh1, C1);

    gemm_kernel<true><<<dim3(C2 / 128, MTOT / 128), 256>>>(z1, W2, b2, sc1, sh1, z2, C1, C2);
    stats_kernel<<<MTOT / 128, 256>>>(z2, C2, sum2, sq2);
    finalize_kernel<<<1, 256>>>(sum2, sq2, g2, be2, sc2, sh2, C2);

    gemm_kernel<true><<<dim3(C3 / 128, MTOT / 128), 256>>>(z2, W3, b3, sc2, sh2, z3, C2, C3);
    stats_kernel<<<MTOT / 128, 256>>>(z3, C3, sum3, sq3);
    finalize_kernel<<<1, 128>>>(sum3, sq3, g3, be3, sc3, sh3, C3);

    trans_norm_kernel<<<dim3(MTOT / 32, C3 / 32), dim3(32, 8)>>>(z3, sc3, sh3, out);
}

// round 5
// speedup vs baseline: 1.1984x; 1.1984x over previous
#include <cuda_runtime.h>
#include <cstdint>

// Problem constants
#define BATCH 4
#define NY 16384
#define NX 4096
#define CY 128
#define CX 256
#define DIMF 384       // CY + CX
#define C1 512
#define C2 256
#define C3 128
#define MTOT (BATCH*NY)   // 65536
#define IEPS 1e-8f
#define BN_EPS 1e-5f

// ---------------- scratch (device globals; no runtime alloc) ----------------
__device__ float g_feat[(size_t)MTOT * DIMF];
__device__ float g_z1[(size_t)MTOT * C1];
__device__ float g_z2[(size_t)MTOT * C2];
__device__ float g_z3[(size_t)MTOT * C3];
__device__ float g_red[1792];
__device__ float g_aff[1792];

__device__ __forceinline__ float tf32r(float x) {
    uint32_t u;
    asm("cvt.rna.tf32.f32 %0, %1;" : "=r"(u) : "f"(x));
    return __uint_as_float(u);
}

// m16n8k8 TF32 mma (portable PTX, runs on Blackwell legacy tensor pipe)
__device__ __forceinline__ void mma8(float* c, const uint32_t* a, const uint32_t* b) {
    asm volatile(
        "mma.sync.aligned.m16n8k8.row.col.f32.tf32.tf32.f32 "
        "{%0,%1,%2,%3}, {%4,%5,%6,%7}, {%8,%9}, {%0,%1,%2,%3};"
        : "+f"(c[0]), "+f"(c[1]), "+f"(c[2]), "+f"(c[3])
        : "r"(a[0]), "r"(a[1]), "r"(a[2]), "r"(a[3]),
          "r"(b[0]), "r"(b[1]));
}

// ---------------- zero kernel ----------------
__global__ void zero_kernel(float* __restrict__ p, int n) {
    int i = blockIdx.x * blockDim.x + threadIdx.x;
    if (i < n) p[i] = 0.0f;
}

// ---------------- KNN + interpolation + concat (exact fp32 op-tree) ----------------
#define NXC 2048
__global__ __launch_bounds__(256)
void knn_interp_kernel(const float* __restrict__ yp, const float* __restrict__ yf,
                       const float* __restrict__ xp, const float* __restrict__ xf,
                       float* __restrict__ feat)
{
    __shared__ float4 s_pt[NXC];
    int b = blockIdx.y;
    int tid = threadIdx.x;
    int n = blockIdx.x * 256 + tid;
    int m = b * NY + n;

    const float* xpb = xp + (size_t)b * NX * 3;
    float px = yp[(size_t)m * 3 + 0];
    float py = yp[(size_t)m * 3 + 1];
    float pz = yp[(size_t)m * 3 + 2];
    float psq = __fadd_rn(__fadd_rn(__fmul_rn(px, px), __fmul_rn(py, py)),
                          __fmul_rn(pz, pz));

    float d0 = 3.4e38f, d1 = 3.4e38f, d2 = 3.4e38f;
    int i0 = 0, i1 = 0, i2 = 0;

    for (int ch = 0; ch < NX; ch += NXC) {
        __syncthreads();
        for (int j = tid; j < NXC; j += 256) {
            const float* xq = xpb + 3 * (size_t)(ch + j);
            float x = xq[0], y = xq[1], z = xq[2];
            float xsq = __fadd_rn(__fadd_rn(__fmul_rn(x, x), __fmul_rn(y, y)),
                                  __fmul_rn(z, z));
            s_pt[j] = make_float4(x, y, z, xsq);
        }
        __syncthreads();
        #pragma unroll 8
        for (int j = 0; j < NXC; j++) {
            float4 q = s_pt[j];
            float dot = __fmaf_rn(pz, q.z, __fmaf_rn(py, q.y, __fmul_rn(px, q.x)));
            float d = __fsub_rn(__fadd_rn(psq, q.w), __fmul_rn(2.0f, dot));
            if (d < d2) {
                int jj = ch + j;
                if (d < d1) {
                    d2 = d1; i2 = i1;
                    if (d < d0) { d1 = d0; i1 = i0; d0 = d; i0 = jj; }
                    else        { d1 = d;  i1 = jj; }
                } else { d2 = d; i2 = jj; }
            }
        }
    }

    float w0 = 1.0f / (d0 + IEPS);
    float w1 = 1.0f / (d1 + IEPS);
    float w2 = 1.0f / (d2 + IEPS);
    float ws = 1.0f / (w0 + w1 + w2);
    w0 *= ws; w1 *= ws; w2 *= ws;

    int lane = tid & 31;
    const float* xfb = xf + (size_t)b * NX * CX;
    unsigned mask = 0xffffffffu;
    for (int s = 0; s < 32; s++) {
        int   j0 = __shfl_sync(mask, i0, s);
        int   j1 = __shfl_sync(mask, i1, s);
        int   j2 = __shfl_sync(mask, i2, s);
        float a0 = __shfl_sync(mask, w0, s);
        float a1 = __shfl_sync(mask, w1, s);
        float a2 = __shfl_sync(mask, w2, s);
        int ms = m - lane + s;
        float* frow = feat + (size_t)ms * DIMF;
        const float4* ysrc = (const float4*)(yf + (size_t)ms * CY);
        ((float4*)frow)[lane] = ysrc[lane];
        const float4* r0 = (const float4*)(xfb + (size_t)j0 * CX);
        const float4* r1 = (const float4*)(xfb + (size_t)j1 * CX);
        const float4* r2 = (const float4*)(xfb + (size_t)j2 * CX);
        float4* dst = (float4*)(frow + CY);
        #pragma unroll
        for (int h = 0; h < 2; h++) {
            int c4 = h * 32 + lane;
            float4 v0 = r0[c4], v1 = r1[c4], v2 = r2[c4];
            float4 o;
            o.x = a0 * v0.x + a1 * v1.x + a2 * v2.x;
            o.y = a0 * v0.y + a1 * v1.y + a2 * v2.y;
            o.z = a0 * v0.z + a1 * v1.z + a2 * v2.z;
            o.w = a0 * v0.w + a1 * v1.w + a2 * v2.w;
            dst[c4] = o;
        }
    }
}

// ---------------- mma.sync 3xTF32 GEMM: C[M,N] = act(A)[M,K] @ W[N,K]^T + bias --------
// Block tile 128x128x16, 8 warps (2m x 4n), each warp 64x32.
// SMEM per buffer (floats): Ah[128][20] Al[128][20] Bh[128][20] Bl[128][20]
// (row stride 20 words -> conflict-free fragment loads). Double buffered.
#define SROW 20
#define ABUF (128 * SROW)          // 2560 floats
#define BUFF (4 * ABUF)            // 10240 floats per buffer
#define GEMM_SMEM (2 * BUFF * 4)   // 81920 bytes

template<bool NORM>
__global__ __launch_bounds__(256, 1)
void mma_gemm_kernel(const float* __restrict__ A, const float* __restrict__ W,
                     const float* __restrict__ bias,
                     const float* __restrict__ scale, const float* __restrict__ shift,
                     float* __restrict__ Cmat, int Kdim, int Ndim)
{
    extern __shared__ float smf[];
    const int tid = threadIdx.x;
    const int w = tid >> 5, lane = tid & 31;
    const int m0 = blockIdx.y * 128, n0 = blockIdx.x * 128;

    const int aRow = tid >> 1;       // staging row 0..127
    const int half = tid & 1;        // which 8-wide k half
    const int sOff = aRow * SROW + half * 8;

    const float* Ap = A + (size_t)(m0 + aRow) * Kdim + half * 8;
    const float* Wp = W + (size_t)(n0 + aRow) * Kdim + half * 8;

    const int nch = Kdim >> 4;

    float acc[4][4][4];
    #pragma unroll
    for (int i = 0; i < 4; i++)
        #pragma unroll
        for (int j = 0; j < 4; j++)
            #pragma unroll
            for (int e = 0; e < 4; e++) acc[i][j][e] = 0.0f;

    float4 ra0, ra1, rb0, rb1;
    ra0 = *(const float4*)(Ap);     ra1 = *(const float4*)(Ap + 4);
    rb0 = *(const float4*)(Wp);     rb1 = *(const float4*)(Wp + 4);

    auto stage = [&](int buf, int kc) {
        float* S = smf + buf * BUFF;
        float av[8] = {ra0.x, ra0.y, ra0.z, ra0.w, ra1.x, ra1.y, ra1.z, ra1.w};
        if (NORM) {
            const float* scp = scale + kc * 16 + half * 8;
            const float* shp = shift + kc * 16 + half * 8;
            #pragma unroll
            for (int j = 0; j < 8; j++)
                av[j] = fmaxf(fmaf(scp[j], av[j], shp[j]), 0.0f);
        }
        float ah[8], al[8];
        #pragma unroll
        for (int j = 0; j < 8; j++) { ah[j] = tf32r(av[j]); al[j] = tf32r(av[j] - ah[j]); }
        *(float4*)(S + sOff)            = make_float4(ah[0], ah[1], ah[2], ah[3]);
        *(float4*)(S + sOff + 4)        = make_float4(ah[4], ah[5], ah[6], ah[7]);
        *(float4*)(S + ABUF + sOff)     = make_float4(al[0], al[1], al[2], al[3]);
        *(float4*)(S + ABUF + sOff + 4) = make_float4(al[4], al[5], al[6], al[7]);

        float bvv[8] = {rb0.x, rb0.y, rb0.z, rb0.w, rb1.x, rb1.y, rb1.z, rb1.w};
        float bh[8], bl[8];
        #pragma unroll
        for (int j = 0; j < 8; j++) { bh[j] = tf32r(bvv[j]); bl[j] = tf32r(bvv[j] - bh[j]); }
        *(float4*)(S + 2 * ABUF + sOff)     = make_float4(bh[0], bh[1], bh[2], bh[3]);
        *(float4*)(S + 2 * ABUF + sOff + 4) = make_float4(bh[4], bh[5], bh[6], bh[7]);
        *(float4*)(S + 3 * ABUF + sOff)     = make_float4(bl[0], bl[1], bl[2], bl[3]);
        *(float4*)(S + 3 * ABUF + sOff + 4) = make_float4(bl[4], bl[5], bl[6], bl[7]);
    };

    stage(0, 0);
    __syncthreads();

    const int mtb = (w & 1) * 64;      // warp m offset in tile
    const int ntb = (w >> 1) * 32;     // warp n offset in tile
    const int fr = lane >> 2;          // fragment row group (0..7)
    const int fc = lane & 3;           // fragment col group (0..3)

    for (int c = 0; c < nch; c++) {
        const float* S = smf + (c & 1) * BUFF;
        if (c + 1 < nch) {
            const float* Ap2 = Ap + (c + 1) * 16;
            const float* Wp2 = Wp + (c + 1) * 16;
            ra0 = *(const float4*)(Ap2); ra1 = *(const float4*)(Ap2 + 4);
            rb0 = *(const float4*)(Wp2); rb1 = *(const float4*)(Wp2 + 4);
        }
        #pragma unroll
        for (int s = 0; s < 2; s++) {
            const int ks = s * 8 + fc;
            uint32_t aH[4][4], aL[4][4], bH[4][2], bL[4][2];
            // A-hi fragments: rows {g, g+8}, cols {t, t+4}
            #pragma unroll
            for (int i = 0; i < 4; i++) {
                const float* pa = S + (mtb + i * 16 + fr) * SROW + ks;
                aH[i][0] = __float_as_uint(pa[0]);
                aH[i][1] = __float_as_uint(pa[8 * SROW]);
                aH[i][2] = __float_as_uint(pa[4]);
                aH[i][3] = __float_as_uint(pa[8 * SROW + 4]);
            }
            // B-hi fragments: k rows {t, t+4}, col g
            #pragma unroll
            for (int j = 0; j < 4; j++) {
                const float* pb = S + 2 * ABUF + (ntb + j * 8 + fr) * SROW + ks;
                bH[j][0] = __float_as_uint(pb[0]);
                bH[j][1] = __float_as_uint(pb[4]);
            }
            #pragma unroll
            for (int i = 0; i < 4; i++)
                #pragma unroll
                for (int j = 0; j < 4; j++)
                    mma8(acc[i][j], aH[i], bH[j]);
            // B-lo
            #pragma unroll
            for (int j = 0; j < 4; j++) {
                const float* pb = S + 3 * ABUF + (ntb + j * 8 + fr) * SROW + ks;
                bL[j][0] = __float_as_uint(pb[0]);
                bL[j][1] = __float_as_uint(pb[4]);
            }
            #pragma unroll
            for (int i = 0; i < 4; i++)
                #pragma unroll
                for (int j = 0; j < 4; j++)
                    mma8(acc[i][j], aH[i], bL[j]);
            // A-lo
            #pragma unroll
            for (int i = 0; i < 4; i++) {
                const float* pa = S + ABUF + (mtb + i * 16 + fr) * SROW + ks;
                aL[i][0] = __float_as_uint(pa[0]);
                aL[i][1] = __float_as_uint(pa[8 * SROW]);
                aL[i][2] = __float_as_uint(pa[4]);
                aL[i][3] = __float_as_uint(pa[8 * SROW + 4]);
            }
            #pragma unroll
            for (int i = 0; i < 4; i++)
                #pragma unroll
                for (int j = 0; j < 4; j++)
                    mma8(acc[i][j], aL[i], bH[j]);
        }
        if (c + 1 < nch) stage((c + 1) & 1, c + 1);
        __syncthreads();
    }

    // epilogue: C fragment rows {g, g+8}, cols {2t, 2t+1}
    const int er = m0 + mtb + fr;
    const int ec = n0 + ntb + fc * 2;
    #pragma unroll
    for (int i = 0; i < 4; i++) {
        #pragma unroll
        for (int j = 0; j < 4; j++) {
            int r = er + i * 16;
            int cc = ec + j * 8;
            float2 b2 = *(const float2*)(bias + cc);
            float2 o0 = make_float2(acc[i][j][0] + b2.x, acc[i][j][1] + b2.y);
            float2 o1 = make_float2(acc[i][j][2] + b2.x, acc[i][j][3] + b2.y);
            *(float2*)(Cmat + (size_t)r * Ndim + cc) = o0;
            *(float2*)(Cmat + (size_t)(r + 8) * Ndim + cc) = o1;
        }
    }
}

// ---------------- per-channel sum / sumsq reduction ----------------
__global__ __launch_bounds__(256)
void stats_kernel(const float* __restrict__ Z, int Cdim,
                  float* __restrict__ sum, float* __restrict__ sq)
{
    int r0 = blockIdx.x * 128;
    for (int c = threadIdx.x; c < Cdim; c += 256) {
        float s = 0.0f, qv = 0.0f;
        const float* p = Z + (size_t)r0 * Cdim + c;
        #pragma unroll 4
        for (int r = 0; r < 128; r++) {
            float v = p[(size_t)r * Cdim];
            s += v;
            qv = fmaf(v, v, qv);
        }
        atomicAdd(&sum[c], s);
        atomicAdd(&sq[c], qv);
    }
}

// ---------------- finalize BN affine ----------------
__global__ void finalize_kernel(const float* __restrict__ sum, const float* __restrict__ sq,
                                const float* __restrict__ g, const float* __restrict__ be,
                                float* __restrict__ scale, float* __restrict__ shift, int Cdim)
{
    int c = blockIdx.x * blockDim.x + threadIdx.x;
    if (c < Cdim) {
        const float invM = 1.0f / (float)MTOT;
        float mean = sum[c] * invM;
        float var  = sq[c] * invM - mean * mean;
        float inv  = rsqrtf(var + BN_EPS);
        float sc   = g[c] * inv;
        scale[c] = sc;
        shift[c] = be[c] - mean * sc;
    }
}

// ---------------- final: normalize+relu layer3 and transpose to [B, C3, NY] ----------------
__global__ __launch_bounds__(256)
void trans_norm_kernel(const float* __restrict__ z3, const float* __restrict__ sc,
                       const float* __restrict__ sh, float* __restrict__ out)
{
    __shared__ float tile[32][33];
    int m0 = blockIdx.x * 32;
    int c0 = blockIdx.y * 32;
    int tx = threadIdx.x, ty = threadIdx.y;
    #pragma unroll
    for (int r = ty; r < 32; r += 8) {
        int c = c0 + tx;
        float v = z3[(size_t)(m0 + r) * C3 + c];
        v = fmaxf(fmaf(sc[c], v, sh[c]), 0.0f);
        tile[r][tx] = v;
    }
    __syncthreads();
    int b = m0 / NY;
    int n0 = m0 - b * NY;
    #pragma unroll
    for (int r = ty; r < 32; r += 8) {
        out[((size_t)b * C3 + c0 + r) * NY + n0 + tx] = tile[tx][r];
    }
}

// ---------------- launch ----------------
extern "C" void kernel_launch(void* const* d_in, const int* in_sizes, int n_in,
                              void* d_out, int out_size)
{
    const float* y_points = (const float*)d_in[0];
    const float* y_feats  = (const float*)d_in[1];
    const float* x_points = (const float*)d_in[2];
    const float* x_feats  = (const float*)d_in[3];
    const float* W1 = (const float*)d_in[4];
    const float* b1 = (const float*)d_in[5];
    const float* g1 = (const float*)d_in[6];
    const float* be1 = (const float*)d_in[7];
    const float* W2 = (const float*)d_in[8];
    const float* b2 = (const float*)d_in[9];
    const float* g2 = (const float*)d_in[10];
    const float* be2 = (const float*)d_in[11];
    const float* W3 = (const float*)d_in[12];
    const float* b3 = (const float*)d_in[13];
    const float* g3 = (const float*)d_in[14];
    const float* be3 = (const float*)d_in[15];
    float* out = (float*)d_out;

    float *feat, *z1, *z2, *z3, *red, *aff;
    cudaGetSymbolAddress((void**)&feat, g_feat);
    cudaGetSymbolAddress((void**)&z1, g_z1);
    cudaGetSymbolAddress((void**)&z2, g_z2);
    cudaGetSymbolAddress((void**)&z3, g_z3);
    cudaGetSymbolAddress((void**)&red, g_red);
    cudaGetSymbolAddress((void**)&aff, g_aff);

    float* sum1 = red + 0;    float* sq1 = red + 512;
    float* sum2 = red + 1024; float* sq2 = red + 1280;
    float* sum3 = red + 1536; float* sq3 = red + 1664;
    float* sc1 = aff + 0;     float* sh1 = aff + 512;
    float* sc2 = aff + 1024;  float* sh2 = aff + 1280;
    float* sc3 = aff + 1536;  float* sh3 = aff + 1664;

    cudaFuncSetAttribute(mma_gemm_kernel<false>, cudaFuncAttributeMaxDynamicSharedMemorySize, GEMM_SMEM);
    cudaFuncSetAttribute(mma_gemm_kernel<true>,  cudaFuncAttributeMaxDynamicSharedMemorySize, GEMM_SMEM);

    zero_kernel<<<7, 256>>>(red, 1792);

    knn_interp_kernel<<<dim3(NY / 256, BATCH), 256>>>(y_points, y_feats, x_points, x_feats, feat);

    mma_gemm_kernel<false><<<dim3(C1 / 128, MTOT / 128), 256, GEMM_SMEM>>>(
        feat, W1, b1, nullptr, nullptr, z1, DIMF, C1);
    stats_kernel<<<MTOT / 128, 256>>>(z1, C1, sum1, sq1);
    finalize_kernel<<<2, 256>>>(sum1, sq1, g1, be1, sc1, sh1, C1);

    mma_gemm_kernel<true><<<dim3(C2 / 128, MTOT / 128), 256, GEMM_SMEM>>>(
        z1, W2, b2, sc1, sh1, z2, C1, C2);
    stats_kernel<<<MTOT / 128, 256>>>(z2, C2, sum2, sq2);
    finalize_kernel<<<1, 256>>>(sum2, sq2, g2, be2, sc2, sh2, C2);

    mma_gemm_kernel<true><<<dim3(C3 / 128, MTOT / 128), 256, GEMM_SMEM>>>(
        z2, W3, b3, sc2, sh2, z3, C2, C3);
    stats_kernel<<<MTOT / 128, 256>>>(z3, C3, sum3, sq3);
    finalize_kernel<<<1, 128>>>(sum3, sq3, g3, be3, sc3, sh3, C3);

    trans_norm_kernel<<<dim3(MTOT / 32, C3 / 32), dim3(32, 8)>>>(z3, sc3, sh3, out);
}

// round 6
// speedup vs baseline: 1.9422x; 1.6207x over previous
#include <cuda_runtime.h>
#include <cuda_bf16.h>
#include <cstdint>

// Problem constants
#define BATCH 4
#define NY 16384
#define NX 4096
#define CY 128
#define CX 256
#define DIMF 384       // CY + CX
#define C1 512
#define C2 256
#define C3 128
#define MTOT (BATCH*NY)   // 65536
#define IEPS 1e-8f
#define BN_EPS 1e-5f

// ---------------- scratch (device globals; no runtime alloc) ----------------
__device__ float g_feat[(size_t)MTOT * DIMF];
__device__ float g_z1[(size_t)MTOT * C1];
__device__ float g_z2[(size_t)MTOT * C2];
__device__ float g_z3[(size_t)MTOT * C3];
__device__ float g_red[1792];
__device__ float g_aff[1792];

// pack two floats to bf16x2 (lo -> low half, hi -> high half)
__device__ __forceinline__ uint32_t cvt2bf(float lo, float hi) {
    uint32_t r;
    asm("cvt.rn.bf16x2.f32 %0, %1, %2;" : "=r"(r) : "f"(hi), "f"(lo));
    return r;
}

// m16n8k16 BF16 mma (portable PTX, Blackwell legacy tensor pipe)
__device__ __forceinline__ void mma16(float* c, const uint32_t* a, const uint32_t* b) {
    asm volatile(
        "mma.sync.aligned.m16n8k16.row.col.f32.bf16.bf16.f32 "
        "{%0,%1,%2,%3}, {%4,%5,%6,%7}, {%8,%9}, {%0,%1,%2,%3};"
        : "+f"(c[0]), "+f"(c[1]), "+f"(c[2]), "+f"(c[3])
        : "r"(a[0]), "r"(a[1]), "r"(a[2]), "r"(a[3]),
          "r"(b[0]), "r"(b[1]));
}

// ---------------- zero kernel ----------------
__global__ void zero_kernel(float* __restrict__ p, int n) {
    int i = blockIdx.x * blockDim.x + threadIdx.x;
    if (i < n) p[i] = 0.0f;
}

// ---------------- KNN + interpolation + concat (exact fp32 op-tree) ----------------
#define NXC 2048
__global__ __launch_bounds__(256)
void knn_interp_kernel(const float* __restrict__ yp, const float* __restrict__ yf,
                       const float* __restrict__ xp, const float* __restrict__ xf,
                       float* __restrict__ feat)
{
    __shared__ float4 s_pt[NXC];
    int b = blockIdx.y;
    int tid = threadIdx.x;
    int n = blockIdx.x * 256 + tid;
    int m = b * NY + n;

    const float* xpb = xp + (size_t)b * NX * 3;
    float px = yp[(size_t)m * 3 + 0];
    float py = yp[(size_t)m * 3 + 1];
    float pz = yp[(size_t)m * 3 + 2];
    float psq = __fadd_rn(__fadd_rn(__fmul_rn(px, px), __fmul_rn(py, py)),
                          __fmul_rn(pz, pz));

    float d0 = 3.4e38f, d1 = 3.4e38f, d2 = 3.4e38f;
    int i0 = 0, i1 = 0, i2 = 0;

    for (int ch = 0; ch < NX; ch += NXC) {
        __syncthreads();
        for (int j = tid; j < NXC; j += 256) {
            const float* xq = xpb + 3 * (size_t)(ch + j);
            float x = xq[0], y = xq[1], z = xq[2];
            float xsq = __fadd_rn(__fadd_rn(__fmul_rn(x, x), __fmul_rn(y, y)),
                                  __fmul_rn(z, z));
            s_pt[j] = make_float4(x, y, z, xsq);
        }
        __syncthreads();
        #pragma unroll 8
        for (int j = 0; j < NXC; j++) {
            float4 q = s_pt[j];
            float dot = __fmaf_rn(pz, q.z, __fmaf_rn(py, q.y, __fmul_rn(px, q.x)));
            float d = __fsub_rn(__fadd_rn(psq, q.w), __fmul_rn(2.0f, dot));
            if (d < d2) {
                int jj = ch + j;
                if (d < d1) {
                    d2 = d1; i2 = i1;
                    if (d < d0) { d1 = d0; i1 = i0; d0 = d; i0 = jj; }
                    else        { d1 = d;  i1 = jj; }
                } else { d2 = d; i2 = jj; }
            }
        }
    }

    float w0 = 1.0f / (d0 + IEPS);
    float w1 = 1.0f / (d1 + IEPS);
    float w2 = 1.0f / (d2 + IEPS);
    float ws = 1.0f / (w0 + w1 + w2);
    w0 *= ws; w1 *= ws; w2 *= ws;

    int lane = tid & 31;
    const float* xfb = xf + (size_t)b * NX * CX;
    unsigned mask = 0xffffffffu;
    for (int s = 0; s < 32; s++) {
        int   j0 = __shfl_sync(mask, i0, s);
        int   j1 = __shfl_sync(mask, i1, s);
        int   j2 = __shfl_sync(mask, i2, s);
        float a0 = __shfl_sync(mask, w0, s);
        float a1 = __shfl_sync(mask, w1, s);
        float a2 = __shfl_sync(mask, w2, s);
        int ms = m - lane + s;
        float* frow = feat + (size_t)ms * DIMF;
        const float4* ysrc = (const float4*)(yf + (size_t)ms * CY);
        ((float4*)frow)[lane] = ysrc[lane];
        const float4* r0 = (const float4*)(xfb + (size_t)j0 * CX);
        const float4* r1 = (const float4*)(xfb + (size_t)j1 * CX);
        const float4* r2 = (const float4*)(xfb + (size_t)j2 * CX);
        float4* dst = (float4*)(frow + CY);
        #pragma unroll
        for (int h = 0; h < 2; h++) {
            int c4 = h * 32 + lane;
            float4 v0 = r0[c4], v1 = r1[c4], v2 = r2[c4];
            float4 o;
            o.x = a0 * v0.x + a1 * v1.x + a2 * v2.x;
            o.y = a0 * v0.y + a1 * v1.y + a2 * v2.y;
            o.z = a0 * v0.z + a1 * v1.z + a2 * v2.z;
            o.w = a0 * v0.w + a1 * v1.w + a2 * v2.w;
            dst[c4] = o;
        }
    }
}

// ---------------- mma.sync 3xBF16 GEMM + fused BN stats ----------------
// C[M,N] = act(A)[M,K] @ W[N,K]^T + bias; per-column sum/sumsq atomically accumulated.
// Block tile 128x128x16, 8 warps (2m x 4n), warp tile 64x32, K-chunk 16.
// SMEM (bf16x2 words, row stride 12): Ah[128][12] Al Bh Bl per buffer; double buffered.
#define SROW_W 12
#define ABUF_W (128 * SROW_W)        // 1536 words
#define BUFF_W (4 * ABUF_W)          // 6144 words per buffer
#define GEMM_SMEM (2 * BUFF_W * 4)   // 49152 bytes

template<bool NORM>
__global__ __launch_bounds__(256)
void mma_gemm_kernel(const float* __restrict__ A, const float* __restrict__ W,
                     const float* __restrict__ bias,
                     const float* __restrict__ scale, const float* __restrict__ shift,
                     float* __restrict__ Cmat,
                     float* __restrict__ gsum, float* __restrict__ gsq,
                     int Kdim, int Ndim)
{
    extern __shared__ uint32_t smw[];
    const int tid = threadIdx.x;
    const int w = tid >> 5, lane = tid & 31;
    const int m0 = blockIdx.y * 128, n0 = blockIdx.x * 128;

    const int aRow = tid >> 1;       // staging row 0..127
    const int half = tid & 1;        // which 8-wide k half of the 16-chunk
    const int sOffW = aRow * SROW_W + half * 4;

    const float* Ap = A + (size_t)(m0 + aRow) * Kdim + half * 8;
    const float* Wp = W + (size_t)(n0 + aRow) * Kdim + half * 8;

    const int nch = Kdim >> 4;

    float acc[4][4][4];
    #pragma unroll
    for (int i = 0; i < 4; i++)
        #pragma unroll
        for (int j = 0; j < 4; j++)
            #pragma unroll
            for (int e = 0; e < 4; e++) acc[i][j][e] = 0.0f;

    float4 ra0, ra1, rb0, rb1;
    ra0 = *(const float4*)(Ap);     ra1 = *(const float4*)(Ap + 4);
    rb0 = *(const float4*)(Wp);     rb1 = *(const float4*)(Wp + 4);

    auto stage = [&](int buf, int kc) {
        uint32_t* S = smw + buf * BUFF_W;
        float av[8] = {ra0.x, ra0.y, ra0.z, ra0.w, ra1.x, ra1.y, ra1.z, ra1.w};
        if (NORM) {
            const float* scp = scale + kc * 16 + half * 8;
            const float* shp = shift + kc * 16 + half * 8;
            #pragma unroll
            for (int j = 0; j < 8; j++)
                av[j] = fmaxf(fmaf(scp[j], av[j], shp[j]), 0.0f);
        }
        uint32_t hw[4], lw[4];
        #pragma unroll
        for (int p = 0; p < 4; p++) {
            uint32_t h = cvt2bf(av[2 * p], av[2 * p + 1]);
            float h0 = __uint_as_float(h << 16);
            float h1 = __uint_as_float(h & 0xffff0000u);
            uint32_t l = cvt2bf(av[2 * p] - h0, av[2 * p + 1] - h1);
            hw[p] = h; lw[p] = l;
        }
        *(uint4*)(S + sOffW)          = make_uint4(hw[0], hw[1], hw[2], hw[3]);
        *(uint4*)(S + ABUF_W + sOffW) = make_uint4(lw[0], lw[1], lw[2], lw[3]);

        float bv[8] = {rb0.x, rb0.y, rb0.z, rb0.w, rb1.x, rb1.y, rb1.z, rb1.w};
        #pragma unroll
        for (int p = 0; p < 4; p++) {
            uint32_t h = cvt2bf(bv[2 * p], bv[2 * p + 1]);
            float h0 = __uint_as_float(h << 16);
            float h1 = __uint_as_float(h & 0xffff0000u);
            uint32_t l = cvt2bf(bv[2 * p] - h0, bv[2 * p + 1] - h1);
            hw[p] = h; lw[p] = l;
        }
        *(uint4*)(S + 2 * ABUF_W + sOffW) = make_uint4(hw[0], hw[1], hw[2], hw[3]);
        *(uint4*)(S + 3 * ABUF_W + sOffW) = make_uint4(lw[0], lw[1], lw[2], lw[3]);
    };

    stage(0, 0);
    __syncthreads();

    const int mtb = (w & 1) * 64;      // warp m offset
    const int ntb = (w >> 1) * 32;     // warp n offset
    const int fr = lane >> 2;          // fragment row group (0..7)
    const int fc = lane & 3;           // fragment k-pair group (0..3)

    for (int c = 0; c < nch; c++) {
        const uint32_t* S = smw + (c & 1) * BUFF_W;
        if (c + 1 < nch) {
            const float* Ap2 = Ap + (c + 1) * 16;
            const float* Wp2 = Wp + (c + 1) * 16;
            ra0 = *(const float4*)(Ap2); ra1 = *(const float4*)(Ap2 + 4);
            rb0 = *(const float4*)(Wp2); rb1 = *(const float4*)(Wp2 + 4);
        }
        uint32_t aH[4][4], aL[4][4], bH[4][2], bL[4][2];
        // A-hi: rows {g, g+8}, k-pair words {t, t+4}
        #pragma unroll
        for (int i = 0; i < 4; i++) {
            const uint32_t* pa = S + (mtb + i * 16 + fr) * SROW_W + fc;
            aH[i][0] = pa[0];
            aH[i][1] = pa[8 * SROW_W];
            aH[i][2] = pa[4];
            aH[i][3] = pa[8 * SROW_W + 4];
        }
        // B-hi: k-pair words {t, t+4}, col g
        #pragma unroll
        for (int j = 0; j < 4; j++) {
            const uint32_t* pb = S + 2 * ABUF_W + (ntb + j * 8 + fr) * SROW_W + fc;
            bH[j][0] = pb[0];
            bH[j][1] = pb[4];
        }
        #pragma unroll
        for (int i = 0; i < 4; i++)
            #pragma unroll
            for (int j = 0; j < 4; j++)
                mma16(acc[i][j], aH[i], bH[j]);
        // B-lo
        #pragma unroll
        for (int j = 0; j < 4; j++) {
            const uint32_t* pb = S + 3 * ABUF_W + (ntb + j * 8 + fr) * SROW_W + fc;
            bL[j][0] = pb[0];
            bL[j][1] = pb[4];
        }
        #pragma unroll
        for (int i = 0; i < 4; i++)
            #pragma unroll
            for (int j = 0; j < 4; j++)
                mma16(acc[i][j], aH[i], bL[j]);
        // A-lo
        #pragma unroll
        for (int i = 0; i < 4; i++) {
            const uint32_t* pa = S + ABUF_W + (mtb + i * 16 + fr) * SROW_W + fc;
            aL[i][0] = pa[0];
            aL[i][1] = pa[8 * SROW_W];
            aL[i][2] = pa[4];
            aL[i][3] = pa[8 * SROW_W + 4];
        }
        #pragma unroll
        for (int i = 0; i < 4; i++)
            #pragma unroll
            for (int j = 0; j < 4; j++)
                mma16(acc[i][j], aL[i], bH[j]);

        if (c + 1 < nch) stage((c + 1) & 1, c + 1);
        __syncthreads();
    }

    // Epilogue: write C (+bias) and accumulate per-column sum/sumsq.
    const int er = m0 + mtb + fr;
    const int ec = n0 + ntb + fc * 2;
    #pragma unroll
    for (int j = 0; j < 4; j++) {
        int cc = ec + j * 8;
        float2 b2 = *(const float2*)(bias + cc);
        float s0 = 0.f, s1 = 0.f, q0 = 0.f, q1 = 0.f;
        #pragma unroll
        for (int i = 0; i < 4; i++) {
            int r = er + i * 16;
            float o00 = acc[i][j][0] + b2.x, o01 = acc[i][j][1] + b2.y;
            float o10 = acc[i][j][2] + b2.x, o11 = acc[i][j][3] + b2.y;
            *(float2*)(Cmat + (size_t)r * Ndim + cc)       = make_float2(o00, o01);
            *(float2*)(Cmat + (size_t)(r + 8) * Ndim + cc) = make_float2(o10, o11);
            s0 += o00 + o10; s1 += o01 + o11;
            q0 += o00 * o00 + o10 * o10;
            q1 += o01 * o01 + o11 * o11;
        }
        #pragma unroll
        for (int off = 4; off < 32; off <<= 1) {
            s0 += __shfl_xor_sync(0xffffffffu, s0, off);
            s1 += __shfl_xor_sync(0xffffffffu, s1, off);
            q0 += __shfl_xor_sync(0xffffffffu, q0, off);
            q1 += __shfl_xor_sync(0xffffffffu, q1, off);
        }
        if (fr == 0) {
            atomicAdd(&gsum[cc], s0);
            atomicAdd(&gsum[cc + 1], s1);
            atomicAdd(&gsq[cc], q0);
            atomicAdd(&gsq[cc + 1], q1);
        }
    }
}

// ---------------- finalize BN affine ----------------
__global__ void finalize_kernel(const float* __restrict__ sum, const float* __restrict__ sq,
                                const float* __restrict__ g, const float* __restrict__ be,
                                float* __restrict__ scale, float* __restrict__ shift, int Cdim)
{
    int c = blockIdx.x * blockDim.x + threadIdx.x;
    if (c < Cdim) {
        const float invM = 1.0f / (float)MTOT;
        float mean = sum[c] * invM;
        float var  = sq[c] * invM - mean * mean;
        float inv  = rsqrtf(var + BN_EPS);
        float sc   = g[c] * inv;
        scale[c] = sc;
        shift[c] = be[c] - mean * sc;
    }
}

// ---------------- final: normalize+relu layer3 and transpose to [B, C3, NY] ----------------
__global__ __launch_bounds__(256)
void trans_norm_kernel(const float* __restrict__ z3, const float* __restrict__ sc,
                       const float* __restrict__ sh, float* __restrict__ out)
{
    __shared__ float tile[32][33];
    int m0 = blockIdx.x * 32;
    int c0 = blockIdx.y * 32;
    int tx = threadIdx.x, ty = threadIdx.y;
    #pragma unroll
    for (int r = ty; r < 32; r += 8) {
        int c = c0 + tx;
        float v = z3[(size_t)(m0 + r) * C3 + c];
        v = fmaxf(fmaf(sc[c], v, sh[c]), 0.0f);
        tile[r][tx] = v;
    }
    __syncthreads();
    int b = m0 / NY;
    int n0 = m0 - b * NY;
    #pragma unroll
    for (int r = ty; r < 32; r += 8) {
        out[((size_t)b * C3 + c0 + r) * NY + n0 + tx] = tile[tx][r];
    }
}

// ---------------- launch ----------------
extern "C" void kernel_launch(void* const* d_in, const int* in_sizes, int n_in,
                              void* d_out, int out_size)
{
    const float* y_points = (const float*)d_in[0];
    const float* y_feats  = (const float*)d_in[1];
    const float* x_points = (const float*)d_in[2];
    const float* x_feats  = (const float*)d_in[3];
    const float* W1 = (const float*)d_in[4];
    const float* b1 = (const float*)d_in[5];
    const float* g1 = (const float*)d_in[6];
    const float* be1 = (const float*)d_in[7];
    const float* W2 = (const float*)d_in[8];
    const float* b2 = (const float*)d_in[9];
    const float* g2 = (const float*)d_in[10];
    const float* be2 = (const float*)d_in[11];
    const float* W3 = (const float*)d_in[12];
    const float* b3 = (const float*)d_in[13];
    const float* g3 = (const float*)d_in[14];
    const float* be3 = (const float*)d_in[15];
    float* out = (float*)d_out;

    float *feat, *z1, *z2, *z3, *red, *aff;
    cudaGetSymbolAddress((void**)&feat, g_feat);
    cudaGetSymbolAddress((void**)&z1, g_z1);
    cudaGetSymbolAddress((void**)&z2, g_z2);
    cudaGetSymbolAddress((void**)&z3, g_z3);
    cudaGetSymbolAddress((void**)&red, g_red);
    cudaGetSymbolAddress((void**)&aff, g_aff);

    float* sum1 = red + 0;    float* sq1 = red + 512;
    float* sum2 = red + 1024; float* sq2 = red + 1280;
    float* sum3 = red + 1536; float* sq3 = red + 1664;
    float* sc1 = aff + 0;     float* sh1 = aff + 512;
    float* sc2 = aff + 1024;  float* sh2 = aff + 1280;
    float* sc3 = aff + 1536;  float* sh3 = aff + 1664;

    cudaFuncSetAttribute(mma_gemm_kernel<false>, cudaFuncAttributeMaxDynamicSharedMemorySize, GEMM_SMEM);
    cudaFuncSetAttribute(mma_gemm_kernel<true>,  cudaFuncAttributeMaxDynamicSharedMemorySize, GEMM_SMEM);

    zero_kernel<<<7, 256>>>(red, 1792);

    knn_interp_kernel<<<dim3(NY / 256, BATCH), 256>>>(y_points, y_feats, x_points, x_feats, feat);

    mma_gemm_kernel<false><<<dim3(C1 / 128, MTOT / 128), 256, GEMM_SMEM>>>(
        feat, W1, b1, nullptr, nullptr, z1, sum1, sq1, DIMF, C1);
    finalize_kernel<<<2, 256>>>(sum1, sq1, g1, be1, sc1, sh1, C1);

    mma_gemm_kernel<true><<<dim3(C2 / 128, MTOT / 128), 256, GEMM_SMEM>>>(
        z1, W2, b2, sc1, sh1, z2, sum2, sq2, C1, C2);
    finalize_kernel<<<1, 256>>>(sum2, sq2, g2, be2, sc2, sh2, C2);

    mma_gemm_kernel<true><<<dim3(C3 / 128, MTOT / 128), 256, GEMM_SMEM>>>(
        z2, W3, b3, sc2, sh2, z3, sum3, sq3, C2, C3);
    finalize_kernel<<<1, 128>>>(sum3, sq3, g3, be3, sc3, sh3, C3);

    trans_norm_kernel<<<dim3(MTOT / 32, C3 / 32), dim3(32, 8)>>>(z3, sc3, sh3, out);
}